// round 2
// baseline (speedup 1.0000x reference)
#include <cuda_runtime.h>
#include <mma.h>
using namespace nvcuda;

#define DIM 2048
#define NH 32
#define HD 64
#define NB 2
#define NQ 4096
#define NKV 512

// scratch (allocation-free rule: __device__ globals)
__device__ float g_q[(size_t)NB * NH * NQ * HD];   // (b,h,n,d) normalized q
__device__ float g_k[(size_t)NB * NH * NKV * HD];  // (b,h,m,d) normalized k
__device__ float g_v[(size_t)NB * NH * NKV * HD];  // (b,h,m,d) v

__device__ __forceinline__ float tf32r(float x) { return wmma::__float_to_tf32(x); }

// ---------------------------------------------------------------------------
// Projection GEMM: C[M][2048] = A[M][2048] * W^T, tiled 128x128, tf32 wmma,
// double-buffered smem with register prefetch.
// KIND 0: q (W row = j, RMSNorm, NSEQ=4096)
// KIND 1: kv (blockIdx.z = 0 -> k: rows h*128+2d, norm; z = 1 -> v: +1, no norm)
// Output layout: dst[((b*NH + h)*NSEQ + n)*64 + d]
// ---------------------------------------------------------------------------
#define BM 128
#define BN 128
#define KC 32
#define KCP 40
#define CLD 132
#define PROJ_SMEM (4 * BM * KCP * 4)   // 81920 B (2 A bufs + 2 B bufs)

template <int KIND>
__global__ __launch_bounds__(256) void proj_kernel(
    const float* __restrict__ A, const float* __restrict__ W0,
    const float* __restrict__ W1)
{
    extern __shared__ float sm[];
    float* Abuf[2] = { sm, sm + BM * KCP };
    float* Bbuf[2] = { sm + 2 * BM * KCP, sm + 3 * BM * KCP };
    constexpr int NSEQ = (KIND == 0) ? NQ : NKV;
    const int mode = (KIND == 0) ? 0 : 1 + blockIdx.z;

    const int m0 = blockIdx.x * BM;
    const int n0 = blockIdx.y * BN;
    const int t = threadIdx.x;
    const int lr = t >> 3;            // 0..31
    const int lc = (t & 7) << 2;      // 0..28 (float4 col)

    // resolve weight row pointers for the 4 B-tile rows this thread loads
    const float* wrow[4];
#pragma unroll
    for (int i = 0; i < 4; i++) {
        int j = n0 + lr + i * 32;
        if (KIND == 0) {
            wrow[i] = W0 + (size_t)j * DIM;
        } else {
            int h = j >> 6, d = j & 63;
            int g = h * 128 + 2 * d + (mode == 2 ? 1 : 0);
            wrow[i] = (g < DIM) ? (W0 + (size_t)g * DIM)
                                : (W1 + (size_t)(g - DIM) * DIM);
        }
    }
    const float* arow[4];
#pragma unroll
    for (int i = 0; i < 4; i++)
        arow[i] = A + (size_t)(m0 + lr + i * 32) * DIM;

    wmma::fragment<wmma::accumulator, 16, 16, 8, float> c[2][4];
#pragma unroll
    for (int i = 0; i < 2; i++)
#pragma unroll
        for (int j = 0; j < 4; j++) wmma::fill_fragment(c[i][j], 0.0f);

    const int warp = t >> 5;
    const int wr = warp & 3;    // row group of 32
    const int wc = warp >> 2;   // col group of 64

    float4 ra[4], rb[4];
    // preload chunk 0
#pragma unroll
    for (int i = 0; i < 4; i++) {
        ra[i] = *(const float4*)&arow[i][lc];
        rb[i] = *(const float4*)&wrow[i][lc];
    }
#pragma unroll
    for (int i = 0; i < 4; i++) {
        float* pa = &Abuf[0][(lr + i * 32) * KCP + lc];
        pa[0] = tf32r(ra[i].x); pa[1] = tf32r(ra[i].y);
        pa[2] = tf32r(ra[i].z); pa[3] = tf32r(ra[i].w);
        float* pb = &Bbuf[0][(lr + i * 32) * KCP + lc];
        pb[0] = tf32r(rb[i].x); pb[1] = tf32r(rb[i].y);
        pb[2] = tf32r(rb[i].z); pb[3] = tf32r(rb[i].w);
    }
    __syncthreads();

    for (int k0 = 0; k0 < DIM; k0 += KC) {
        const int p = (k0 / KC) & 1;
        const bool more = (k0 + KC) < DIM;
        if (more) {
#pragma unroll
            for (int i = 0; i < 4; i++) {
                ra[i] = *(const float4*)&arow[i][k0 + KC + lc];
                rb[i] = *(const float4*)&wrow[i][k0 + KC + lc];
            }
        }
        const float* As = Abuf[p];
        const float* Bs = Bbuf[p];
#pragma unroll
        for (int ks = 0; ks < KC; ks += 8) {
            wmma::fragment<wmma::matrix_a, 16, 16, 8, wmma::precision::tf32, wmma::row_major> a0, a1;
            wmma::load_matrix_sync(a0, &As[(wr * 32) * KCP + ks], KCP);
            wmma::load_matrix_sync(a1, &As[(wr * 32 + 16) * KCP + ks], KCP);
#pragma unroll
            for (int nt = 0; nt < 4; nt++) {
                wmma::fragment<wmma::matrix_b, 16, 16, 8, wmma::precision::tf32, wmma::col_major> b;
                wmma::load_matrix_sync(b, &Bs[(wc * 64 + nt * 16) * KCP + ks], KCP);
                wmma::mma_sync(c[0][nt], a0, b, c[0][nt]);
                wmma::mma_sync(c[1][nt], a1, b, c[1][nt]);
            }
        }
        if (more) {
#pragma unroll
            for (int i = 0; i < 4; i++) {
                float* pa = &Abuf[p ^ 1][(lr + i * 32) * KCP + lc];
                pa[0] = tf32r(ra[i].x); pa[1] = tf32r(ra[i].y);
                pa[2] = tf32r(ra[i].z); pa[3] = tf32r(ra[i].w);
                float* pb = &Bbuf[p ^ 1][(lr + i * 32) * KCP + lc];
                pb[0] = tf32r(rb[i].x); pb[1] = tf32r(rb[i].y);
                pb[2] = tf32r(rb[i].z); pb[3] = tf32r(rb[i].w);
            }
        }
        __syncthreads();
    }

    // epilogue: stage to shared, per-head RMSNorm, write (b,h,seq,d)
    float* Cs = sm;  // BM*CLD floats (overlays buffers, 67584 B <= 81920 B)
#pragma unroll
    for (int i = 0; i < 2; i++)
#pragma unroll
        for (int nt = 0; nt < 4; nt++)
            wmma::store_matrix_sync(&Cs[(wr * 32 + i * 16) * CLD + wc * 64 + nt * 16],
                                    c[i][nt], CLD, wmma::mem_row_major);
    __syncthreads();

    __shared__ float sscale[BM * 2];
    {
        int row = t >> 1, g = t & 1;
        float s = 1.0f;
        if (mode != 2) {
            const float* cr = &Cs[row * CLD + g * 64];
            float ss = 0.0f;
#pragma unroll
            for (int d = 0; d < 64; d++) { float v = cr[d]; ss += v * v; }
            s = rsqrtf(ss * (1.0f / 64.0f) + 1e-6f);
        }
        sscale[row * 2 + g] = s;
    }
    __syncthreads();

    float* dst = (mode == 0) ? g_q : (mode == 1) ? g_k : g_v;
#pragma unroll
    for (int it = 0; it < 16; it++) {
        int f = t + it * 256;        // 0..4095 float4 slots
        int row = f >> 5;
        int c4 = f & 31;
        int j = c4 << 2;             // col in tile
        int g = j >> 6;
        int d = j & 63;
        int gi = m0 + row;
        int bb = gi / NSEQ, n = gi % NSEQ;
        int h = (n0 >> 6) + g;
        float sc = sscale[row * 2 + g];
        const float* cr = &Cs[row * CLD + j];
        float4 v;
        v.x = cr[0] * sc; v.y = cr[1] * sc; v.z = cr[2] * sc; v.w = cr[3] * sc;
        *(float4*)&dst[(((size_t)bb * NH + h) * NSEQ + n) * HD + d] = v;
    }
}

// ---------------------------------------------------------------------------
// Fused attention: per (b, h, 32-query tile). 256 threads (8 warps), each warp
// owns one 16x16 tile. Full 32x512 score row in smem, 2-pass softmax with
// 1/rowsum folded into the output epilogue. Double-buffered K/V tiles.
// ---------------------------------------------------------------------------
#define TQ 32
#define QLD 72
#define KLD 72
#define SLD 520
// smem float offsets
#define OFF_Q    0
#define OFF_KV0  2304
#define OFF_KV1  6912
#define OFF_S    11520
#define OFF_PM   28160
#define OFF_RS   28416
#define ATTN_FLOATS 28448
#define ATTN_SMEM (ATTN_FLOATS * 4)   // 113792 B -> 2 CTAs/SM

__global__ __launch_bounds__(256) void attn_kernel(float* __restrict__ out)
{
    extern __shared__ float sm[];
    float* Qs = sm + OFF_Q;                         // TQ x QLD
    float* kvbuf[2] = { sm + OFF_KV0, sm + OFF_KV1 };  // 64 x KLD each
    float* Ss = sm + OFF_S;                          // TQ x SLD
    float* pm = sm + OFF_PM;                         // 256 partials
    float* rstat = sm + OFF_RS;                      // 32 row stats

    const int t = threadIdx.x;
    const int q0 = blockIdx.x * TQ;
    const int h = blockIdx.y;
    const int b = blockIdx.z;

    const float* qbase = g_q + (((size_t)b * NH + h) * NQ + q0) * HD;
    const float* kbase = g_k + ((size_t)b * NH + h) * NKV * HD;
    const float* vbase = g_v + ((size_t)b * NH + h) * NKV * HD;

    const int warp = t >> 5;
    const int rowt = warp & 1;     // 16-row tile of the 32 queries
    const int ct = warp >> 1;      // 16-col tile (0..3) within a 64-wide block

    // load Q tile, fold in softmax scale 1/8 (2 float4 per thread)
#pragma unroll
    for (int it = 0; it < 2; it++) {
        int f = t + it * 256;
        int r = f >> 4, c4 = (f & 15) << 2;
        float4 v = *(const float4*)&qbase[r * HD + c4];
        float* p = &Qs[r * QLD + c4];
        p[0] = tf32r(v.x * 0.125f); p[1] = tf32r(v.y * 0.125f);
        p[2] = tf32r(v.z * 0.125f); p[3] = tf32r(v.w * 0.125f);
    }

    float4 rv[4];
    // preload K tile 0
#pragma unroll
    for (int it = 0; it < 4; it++) {
        int f = t + it * 256;
        int r = f >> 4, c4 = (f & 15) << 2;
        rv[it] = *(const float4*)&kbase[r * HD + c4];
    }
#pragma unroll
    for (int it = 0; it < 4; it++) {
        int f = t + it * 256;
        int r = f >> 4, c4 = (f & 15) << 2;
        float* p = &kvbuf[0][r * KLD + c4];
        p[0] = tf32r(rv[it].x); p[1] = tf32r(rv[it].y);
        p[2] = tf32r(rv[it].z); p[3] = tf32r(rv[it].w);
    }
    __syncthreads();

    // S = (Q/8) K^T  -> Ss
    for (int kt = 0; kt < 8; kt++) {
        const int p = kt & 1;
        if (kt < 7) {
#pragma unroll
            for (int it = 0; it < 4; it++) {
                int f = t + it * 256;
                int r = f >> 4, c4 = (f & 15) << 2;
                rv[it] = *(const float4*)&kbase[((kt + 1) * 64 + r) * HD + c4];
            }
        }
        wmma::fragment<wmma::accumulator, 16, 16, 8, float> s;
        wmma::fill_fragment(s, 0.0f);
#pragma unroll
        for (int ks = 0; ks < 8; ks++) {
            wmma::fragment<wmma::matrix_a, 16, 16, 8, wmma::precision::tf32, wmma::row_major> a;
            wmma::load_matrix_sync(a, &Qs[rowt * 16 * QLD + ks * 8], QLD);
            wmma::fragment<wmma::matrix_b, 16, 16, 8, wmma::precision::tf32, wmma::col_major> bb;
            wmma::load_matrix_sync(bb, &kvbuf[p][ct * 16 * KLD + ks * 8], KLD);
            wmma::mma_sync(s, a, bb, s);
        }
        wmma::store_matrix_sync(&Ss[rowt * 16 * SLD + kt * 64 + ct * 16], s, SLD,
                                wmma::mem_row_major);
        if (kt < 7) {
#pragma unroll
            for (int it = 0; it < 4; it++) {
                int f = t + it * 256;
                int r = f >> 4, c4 = (f & 15) << 2;
                float* q = &kvbuf[p ^ 1][r * KLD + c4];
                q[0] = tf32r(rv[it].x); q[1] = tf32r(rv[it].y);
                q[2] = tf32r(rv[it].z); q[3] = tf32r(rv[it].w);
            }
        }
        __syncthreads();
    }

    // prefetch V tile 0 (held across softmax)
#pragma unroll
    for (int it = 0; it < 4; it++) {
        int f = t + it * 256;
        int r = f >> 4, c4 = (f & 15) << 2;
        rv[it] = *(const float4*)&vbase[r * HD + c4];
    }

    // 2-pass softmax over 512 per row; 1/sum folded into epilogue
    {
        const int row = t >> 3, seg = t & 7;
        float* base = &Ss[row * SLD + seg * 64];
        float m = -1e30f;
#pragma unroll 8
        for (int c = 0; c < 64; c++) m = fmaxf(m, base[c]);
        pm[t] = m;
        __syncthreads();
        if (t < TQ) {
            float mm = pm[t * 8];
#pragma unroll
            for (int j = 1; j < 8; j++) mm = fmaxf(mm, pm[t * 8 + j]);
            rstat[t] = mm;
        }
        __syncthreads();
        float mm = rstat[row];
        float ssum = 0.0f;
#pragma unroll 8
        for (int c = 0; c < 64; c++) {
            float e = __expf(base[c] - mm);
            ssum += e;
            base[c] = tf32r(e);
        }
        pm[t] = ssum;
        __syncthreads();
        if (t < TQ) {
            float s = 0.0f;
#pragma unroll
            for (int j = 0; j < 8; j++) s += pm[t * 8 + j];
            rstat[t] = 1.0f / s;
        }
        __syncthreads();
    }

    // stage V tile 0
#pragma unroll
    for (int it = 0; it < 4; it++) {
        int f = t + it * 256;
        int r = f >> 4, c4 = (f & 15) << 2;
        float* p = &kvbuf[0][r * KLD + c4];
        p[0] = tf32r(rv[it].x); p[1] = tf32r(rv[it].y);
        p[2] = tf32r(rv[it].z); p[3] = tf32r(rv[it].w);
    }
    __syncthreads();

    // O = P V, fragment accumulation across 8 V tiles
    wmma::fragment<wmma::accumulator, 16, 16, 8, float> o;
    wmma::fill_fragment(o, 0.0f);
    for (int vt = 0; vt < 8; vt++) {
        const int p = vt & 1;
        if (vt < 7) {
#pragma unroll
            for (int it = 0; it < 4; it++) {
                int f = t + it * 256;
                int r = f >> 4, c4 = (f & 15) << 2;
                rv[it] = *(const float4*)&vbase[((vt + 1) * 64 + r) * HD + c4];
            }
        }
#pragma unroll
        for (int ks = 0; ks < 8; ks++) {
            wmma::fragment<wmma::matrix_a, 16, 16, 8, wmma::precision::tf32, wmma::row_major> a;
            wmma::load_matrix_sync(a, &Ss[rowt * 16 * SLD + vt * 64 + ks * 8], SLD);
            wmma::fragment<wmma::matrix_b, 16, 16, 8, wmma::precision::tf32, wmma::row_major> bb;
            wmma::load_matrix_sync(bb, &kvbuf[p][(ks * 8) * KLD + ct * 16], KLD);
            wmma::mma_sync(o, a, bb, o);
        }
        if (vt < 7) {
#pragma unroll
            for (int it = 0; it < 4; it++) {
                int f = t + it * 256;
                int r = f >> 4, c4 = (f & 15) << 2;
                float* q = &kvbuf[p ^ 1][r * KLD + c4];
                q[0] = tf32r(rv[it].x); q[1] = tf32r(rv[it].y);
                q[2] = tf32r(rv[it].z); q[3] = tf32r(rv[it].w);
            }
        }
        __syncthreads();
    }

    // stage O into Qs, scale by 1/rowsum, write (b, n, h*64+d)
    wmma::store_matrix_sync(&Qs[rowt * 16 * QLD + ct * 16], o, QLD, wmma::mem_row_major);
    __syncthreads();
#pragma unroll
    for (int it = 0; it < 2; it++) {
        int f = t + it * 256;
        int r = f >> 4, c4 = (f & 15) << 2;
        float rinv = rstat[r];
        const float* p = &Qs[r * QLD + c4];
        float4 v;
        v.x = p[0] * rinv; v.y = p[1] * rinv; v.z = p[2] * rinv; v.w = p[3] * rinv;
        *(float4*)&out[((size_t)b * NQ + q0 + r) * DIM + h * HD + c4] = v;
    }
}

// ---------------------------------------------------------------------------
extern "C" void kernel_launch(void* const* d_in, const int* in_sizes, int n_in,
                              void* d_out, int out_size)
{
    const float* x  = (const float*)d_in[0];
    const float* cx = (const float*)d_in[1];
    const float* Wq = (const float*)d_in[2];
    const float* Wk = (const float*)d_in[3];
    const float* Wv = (const float*)d_in[4];
    float* out = (float*)d_out;

    cudaFuncSetAttribute((const void*)proj_kernel<0>,
                         cudaFuncAttributeMaxDynamicSharedMemorySize, PROJ_SMEM);
    cudaFuncSetAttribute((const void*)proj_kernel<1>,
                         cudaFuncAttributeMaxDynamicSharedMemorySize, PROJ_SMEM);
    cudaFuncSetAttribute((const void*)attn_kernel,
                         cudaFuncAttributeMaxDynamicSharedMemorySize, ATTN_SMEM);

    // q projection: M = 2*4096 = 8192 rows
    proj_kernel<0><<<dim3(64, 16), 256, PROJ_SMEM>>>(x, Wq, Wq);
    // k + v projections fused: M = 1024 rows, z selects k vs v
    proj_kernel<1><<<dim3(8, 16, 2), 256, PROJ_SMEM>>>(cx, Wk, Wv);
    // fused attention
    attn_kernel<<<dim3(NQ / TQ, NH, NB), 256, ATTN_SMEM>>>(out);
}

// round 4
// speedup vs baseline: 2.4287x; 2.4287x over previous
#include <cuda_runtime.h>
#include <cuda_fp16.h>
#include <cstdint>
#include <mma.h>
using namespace nvcuda;

#define DIM 2048
#define NH 32
#define HD 64
#define NB 2
#define NQ 4096
#define NKV 512

// scratch (allocation-free rule: __device__ globals) — fp16, pre-normalized
__device__ __half g_q[(size_t)NB * NH * NQ * HD];   // (b,h,n,d) rmsnorm(q)*0.125
__device__ __half g_k[(size_t)NB * NH * NKV * HD];  // (b,h,m,d) rmsnorm(k)
__device__ __half g_v[(size_t)NB * NH * NKV * HD];  // (b,h,m,d) v

// ===========================================================================
// Projection GEMM (fp16 wmma m16n16k16): C[M][2048] = A * W^T, 128x128 tiles.
// MODE 0: q (rows j of Wq, RMSNorm * 0.125, NSEQ=4096)
// MODE 1: k (rows h*128+2d of [Wk;Wv], RMSNorm, NSEQ=512)
// MODE 2: v (rows h*128+2d+1,           no norm, NSEQ=512)
// Output: dst[((b*NH + h)*NSEQ + n)*64 + d] as __half
// ===========================================================================
#define BM 128
#define BN 128
#define KC 32
#define KCP2 40          // half elements per smem row (80 B)
#define CLD2 136         // epilogue half stride (272 B)
#define PROJ_SMEM (BM * CLD2 * 2)   // 34816 B (mainloop 20480 B fits under it)

template <int MODE>
__global__ __launch_bounds__(256, 2) void proj_fp16(
    const float* __restrict__ A, const float* __restrict__ W0,
    const float* __restrict__ W1)
{
    extern __shared__ char smraw[];
    __half* As = (__half*)smraw;                  // BM x KCP2
    __half* Bs = As + BM * KCP2;                  // BN x KCP2
    constexpr int NSEQ = (MODE == 0) ? NQ : NKV;

    const int m0 = blockIdx.x * BM;
    const int n0 = blockIdx.y * BN;
    const int t = threadIdx.x;
    const int lr = t >> 3;            // 0..31
    const int lc = (t & 7) << 2;      // float4 col 0..28

    const float* wrow[4];
#pragma unroll
    for (int i = 0; i < 4; i++) {
        int j = n0 + lr + i * 32;
        if (MODE == 0) {
            wrow[i] = W0 + (size_t)j * DIM;
        } else {
            int h = j >> 6, d = j & 63;
            int g = h * 128 + 2 * d + (MODE == 2 ? 1 : 0);
            wrow[i] = (g < DIM) ? (W0 + (size_t)g * DIM)
                                : (W1 + (size_t)(g - DIM) * DIM);
        }
    }

    wmma::fragment<wmma::accumulator, 16, 16, 16, float> c[2][4];
#pragma unroll
    for (int i = 0; i < 2; i++)
#pragma unroll
        for (int j = 0; j < 4; j++) wmma::fill_fragment(c[i][j], 0.0f);

    const int warp = t >> 5;
    const int wr = warp & 3;    // 32-row group
    const int wc = warp >> 2;   // 64-col group

    for (int k0 = 0; k0 < DIM; k0 += KC) {
#pragma unroll
        for (int i = 0; i < 4; i++) {
            float4 v = *(const float4*)&A[(size_t)(m0 + lr + i * 32) * DIM + k0 + lc];
            __half* p = &As[(lr + i * 32) * KCP2 + lc];
            p[0] = __float2half_rn(v.x); p[1] = __float2half_rn(v.y);
            p[2] = __float2half_rn(v.z); p[3] = __float2half_rn(v.w);
        }
#pragma unroll
        for (int i = 0; i < 4; i++) {
            float4 v = *(const float4*)&wrow[i][k0 + lc];
            __half* p = &Bs[(lr + i * 32) * KCP2 + lc];
            p[0] = __float2half_rn(v.x); p[1] = __float2half_rn(v.y);
            p[2] = __float2half_rn(v.z); p[3] = __float2half_rn(v.w);
        }
        __syncthreads();
#pragma unroll
        for (int ks = 0; ks < KC; ks += 16) {
            wmma::fragment<wmma::matrix_a, 16, 16, 16, __half, wmma::row_major> a0, a1;
            wmma::load_matrix_sync(a0, &As[(wr * 32) * KCP2 + ks], KCP2);
            wmma::load_matrix_sync(a1, &As[(wr * 32 + 16) * KCP2 + ks], KCP2);
#pragma unroll
            for (int nt = 0; nt < 4; nt++) {
                wmma::fragment<wmma::matrix_b, 16, 16, 16, __half, wmma::col_major> b;
                wmma::load_matrix_sync(b, &Bs[(wc * 64 + nt * 16) * KCP2 + ks], KCP2);
                wmma::mma_sync(c[0][nt], a0, b, c[0][nt]);
                wmma::mma_sync(c[1][nt], a1, b, c[1][nt]);
            }
        }
        __syncthreads();
    }

    // epilogue: convert acc -> half, stage, per-head RMSNorm, write half scratch
    __half* Cs = (__half*)smraw;   // BM x CLD2 halves
#pragma unroll
    for (int i = 0; i < 2; i++)
#pragma unroll
        for (int nt = 0; nt < 4; nt++) {
            wmma::fragment<wmma::accumulator, 16, 16, 16, __half> ch;
#pragma unroll
            for (int e = 0; e < ch.num_elements; e++)
                ch.x[e] = __float2half_rn(c[i][nt].x[e]);
            wmma::store_matrix_sync(&Cs[(wr * 32 + i * 16) * CLD2 + wc * 64 + nt * 16],
                                    ch, CLD2, wmma::mem_row_major);
        }
    __syncthreads();

    __shared__ float sscale[BM * 2];
    {
        int row = t >> 1, g = t & 1;
        float s = 1.0f;
        if (MODE != 2) {
            const __half* cr = &Cs[row * CLD2 + g * 64];
            float ss = 0.0f;
#pragma unroll
            for (int d = 0; d < 64; d++) { float v = __half2float(cr[d]); ss += v * v; }
            s = rsqrtf(ss * (1.0f / 64.0f) + 1e-6f);
            if (MODE == 0) s *= 0.125f;   // fold softmax scale into q
        }
        sscale[row * 2 + g] = s;
    }
    __syncthreads();

    __half* dst = (MODE == 0) ? g_q : (MODE == 1) ? g_k : g_v;
#pragma unroll
    for (int it = 0; it < 16; it++) {
        int f = t + it * 256;        // 4096 chunks of 4 halves
        int row = f >> 5;
        int j = (f & 31) << 2;       // half col in tile
        int g = j >> 6;
        int d = j & 63;
        int gi = m0 + row;
        int bb = gi / NSEQ, n = gi % NSEQ;
        int h = (n0 >> 6) + g;
        float sc = sscale[row * 2 + g];
        const __half* cr = &Cs[row * CLD2 + j];
        __half o[4];
#pragma unroll
        for (int u = 0; u < 4; u++)
            o[u] = __float2half_rn(__half2float(cr[u]) * sc);
        *(uint2*)&dst[(((size_t)bb * NH + h) * NSEQ + n) * HD + d] = *(uint2*)o;
    }
}

// ===========================================================================
// Fused attention (fp16 operands, fp32 softmax): per (b, h, 32-query tile).
// Full 32x512 score row in fp32 smem; P converted in place to half
// (segment-local layout); 2-pass softmax, 1/sum folded into epilogue.
// ===========================================================================
#define TQ 32
#define QLD2 72            // half stride for Q/KV tiles
#define SLD 516            // float stride for S rows
#define PROW_H (SLD * 2)   // 1032 halves per P row (same bytes as S row)
// byte offsets in dynamic smem
#define OFF_Q   0                        // 32x72 halves  = 4608 B
#define OFF_KV  4608                     // 64x72 halves  = 9216 B
#define OFF_S   13824                    // 32x516 floats = 66048 B
#define OFF_PM  79872                    // 128 floats
#define OFF_RS  80384                    // 32 floats
#define ATTN_SMEM 80512

__global__ __launch_bounds__(128) void attn_kernel(float* __restrict__ out)
{
    extern __shared__ char smraw[];
    __half* Qs = (__half*)(smraw + OFF_Q);
    __half* KVs = (__half*)(smraw + OFF_KV);
    float* Ss = (float*)(smraw + OFF_S);
    __half* Ps = (__half*)(smraw + OFF_S);   // same bytes, segment-local layout
    float* pm = (float*)(smraw + OFF_PM);
    float* rstat = (float*)(smraw + OFF_RS);

    const int t = threadIdx.x;
    const int q0 = blockIdx.x * TQ;
    const int h = blockIdx.y;
    const int b = blockIdx.z;

    const __half* qbase = g_q + (((size_t)b * NH + h) * NQ + q0) * HD;
    const __half* kbase = g_k + ((size_t)b * NH + h) * NKV * HD;
    const __half* vbase = g_v + ((size_t)b * NH + h) * NKV * HD;

    // load Q tile (raw copy — scale+norm already folded in)
#pragma unroll
    for (int it = 0; it < 4; it++) {
        int f = t + it * 128;             // 512 chunks of 4 halves (16/row)
        int r = f >> 4, c4 = (f & 15) << 2;
        *(uint2*)&Qs[r * QLD2 + c4] = *(const uint2*)&qbase[r * HD + c4];
    }

    const int warp = t >> 5;
    const int rowt = warp & 1;
    const int ct0 = (warp >> 1) * 2;

    // S = Q K^T
    for (int kt = 0; kt < 8; kt++) {
        __syncthreads();
#pragma unroll
        for (int it = 0; it < 8; it++) {
            int f = t + it * 128;         // 1024 chunks (16/row, 64 rows)
            int r = f >> 4, c4 = (f & 15) << 2;
            *(uint2*)&KVs[r * QLD2 + c4] = *(const uint2*)&kbase[(kt * 64 + r) * HD + c4];
        }
        __syncthreads();
#pragma unroll
        for (int ctt = 0; ctt < 2; ctt++) {
            int ct = ct0 + ctt;
            wmma::fragment<wmma::accumulator, 16, 16, 16, float> s;
            wmma::fill_fragment(s, 0.0f);
#pragma unroll
            for (int ks = 0; ks < 4; ks++) {
                wmma::fragment<wmma::matrix_a, 16, 16, 16, __half, wmma::row_major> a;
                wmma::load_matrix_sync(a, &Qs[rowt * 16 * QLD2 + ks * 16], QLD2);
                wmma::fragment<wmma::matrix_b, 16, 16, 16, __half, wmma::col_major> bb;
                wmma::load_matrix_sync(bb, &KVs[ct * 16 * QLD2 + ks * 16], QLD2);
                wmma::mma_sync(s, a, bb, s);
            }
            wmma::store_matrix_sync(&Ss[rowt * 16 * SLD + kt * 64 + ct * 16], s, SLD,
                                    wmma::mem_row_major);
        }
    }
    __syncthreads();

    // softmax: pass 1 max, pass 2 exp -> half P in place (chunked + fenced)
    {
        const int row = t >> 2, seg = t & 3;
        float* fb = &Ss[row * SLD + seg * 128];
        __half* hb = &Ps[row * PROW_H + seg * 256];
        float m = -1e30f;
#pragma unroll 16
        for (int c = 0; c < 128; c++) m = fmaxf(m, fb[c]);
        pm[t] = m;
        __syncthreads();
        if (t < TQ)
            rstat[t] = fmaxf(fmaxf(pm[t * 4], pm[t * 4 + 1]),
                             fmaxf(pm[t * 4 + 2], pm[t * 4 + 3]));
        __syncthreads();
        float mm = rstat[row];
        float ssum = 0.0f;
        for (int ch = 0; ch < 8; ch++) {
            float e[16];
#pragma unroll
            for (int i = 0; i < 16; i++) {
                e[i] = __expf(fb[ch * 16 + i] - mm);
                ssum += e[i];
            }
            asm volatile("" ::: "memory");
#pragma unroll
            for (int i = 0; i < 16; i++)
                hb[ch * 16 + i] = __float2half_rn(e[i]);
            asm volatile("" ::: "memory");
        }
        pm[t] = ssum;
        __syncthreads();
        if (t < TQ)
            rstat[t] = 1.0f / (pm[t * 4] + pm[t * 4 + 1] + pm[t * 4 + 2] + pm[t * 4 + 3]);
        __syncthreads();
    }

    // O = P V over 8 V tiles
    wmma::fragment<wmma::accumulator, 16, 16, 16, float> o[2];
    wmma::fill_fragment(o[0], 0.0f);
    wmma::fill_fragment(o[1], 0.0f);
    for (int vt = 0; vt < 8; vt++) {
        __syncthreads();
#pragma unroll
        for (int it = 0; it < 8; it++) {
            int f = t + it * 128;
            int r = f >> 4, c4 = (f & 15) << 2;
            *(uint2*)&KVs[r * QLD2 + c4] = *(const uint2*)&vbase[(vt * 64 + r) * HD + c4];
        }
        __syncthreads();
#pragma unroll
        for (int ks = 0; ks < 4; ks++) {
            int c0 = vt * 64 + ks * 16;
            const __half* pa = Ps + rowt * 16 * PROW_H + ((c0 >> 7) << 8) + (c0 & 127);
            wmma::fragment<wmma::matrix_a, 16, 16, 16, __half, wmma::row_major> a;
            wmma::load_matrix_sync(a, pa, PROW_H);
#pragma unroll
            for (int ctt = 0; ctt < 2; ctt++) {
                int ct = ct0 + ctt;
                wmma::fragment<wmma::matrix_b, 16, 16, 16, __half, wmma::row_major> bb;
                wmma::load_matrix_sync(bb, &KVs[(ks * 16) * QLD2 + ct * 16], QLD2);
                wmma::mma_sync(o[ctt], a, bb, o[ctt]);
            }
        }
    }
    __syncthreads();

    // stage O (reuse S region as float), scale by 1/rowsum, write out
    float* Osf = (float*)(smraw + OFF_S);
    wmma::store_matrix_sync(&Osf[rowt * 16 * 72 + ct0 * 16], o[0], 72, wmma::mem_row_major);
    wmma::store_matrix_sync(&Osf[rowt * 16 * 72 + (ct0 + 1) * 16], o[1], 72, wmma::mem_row_major);
    __syncthreads();
#pragma unroll
    for (int it = 0; it < 4; it++) {
        int f = t + it * 128;             // 512 chunks of float4 (16/row)
        int r = f >> 4, c4 = (f & 15) << 2;
        float rinv = rstat[r];
        const float* p = &Osf[r * 72 + c4];
        float4 v;
        v.x = p[0] * rinv; v.y = p[1] * rinv; v.z = p[2] * rinv; v.w = p[3] * rinv;
        *(float4*)&out[((size_t)b * NQ + q0 + r) * DIM + h * HD + c4] = v;
    }
}

// ---------------------------------------------------------------------------
extern "C" void kernel_launch(void* const* d_in, const int* in_sizes, int n_in,
                              void* d_out, int out_size)
{
    const float* x  = (const float*)d_in[0];
    const float* cx = (const float*)d_in[1];
    const float* Wq = (const float*)d_in[2];
    const float* Wk = (const float*)d_in[3];
    const float* Wv = (const float*)d_in[4];
    float* out = (float*)d_out;

    cudaFuncSetAttribute((const void*)proj_fp16<0>,
                         cudaFuncAttributeMaxDynamicSharedMemorySize, PROJ_SMEM);
    cudaFuncSetAttribute((const void*)proj_fp16<1>,
                         cudaFuncAttributeMaxDynamicSharedMemorySize, PROJ_SMEM);
    cudaFuncSetAttribute((const void*)proj_fp16<2>,
                         cudaFuncAttributeMaxDynamicSharedMemorySize, PROJ_SMEM);
    cudaFuncSetAttribute((const void*)attn_kernel,
                         cudaFuncAttributeMaxDynamicSharedMemorySize, ATTN_SMEM);

    // q projection: 8192 rows -> 64 x 16 tiles
    proj_fp16<0><<<dim3(64, 16), 256, PROJ_SMEM>>>(x, Wq, Wq);
    // k / v projections: 1024 rows -> 8 x 16 tiles, interleaved row gather
    proj_fp16<1><<<dim3(8, 16), 256, PROJ_SMEM>>>(cx, Wk, Wv);
    proj_fp16<2><<<dim3(8, 16), 256, PROJ_SMEM>>>(cx, Wk, Wv);
    // fused attention
    attn_kernel<<<dim3(NQ / TQ, NH, NB), 128, ATTN_SMEM>>>(out);
}

// round 5
// speedup vs baseline: 3.4904x; 1.4371x over previous
#include <cuda_runtime.h>
#include <cuda_fp16.h>
#include <cstdint>
#include <mma.h>
using namespace nvcuda;

#define DIM 2048
#define NH 32
#define HD 64
#define NB 2
#define NQ 4096
#define NKV 512

// scratch (allocation-free rule: __device__ globals) — fp16, pre-normalized
__device__ __half g_q[(size_t)NB * NH * NQ * HD];   // (b,h,n,d) rmsnorm(q)*0.125
__device__ __half g_k[(size_t)NB * NH * NKV * HD];  // (b,h,m,d) rmsnorm(k)
__device__ __half g_v[(size_t)NB * NH * HD * NKV];  // (b,h,d,m)  v TRANSPOSED

// ===========================================================================
// Projection GEMM (fp16 wmma m16n16k16): C[M][2048] = A * W^T, 128x128 tiles.
// MODE 0: q (rows j of Wq, RMSNorm * 0.125, NSEQ=4096)
// MODE 1: k (rows h*128+2d of [Wk;Wv], RMSNorm, NSEQ=512)
// MODE 2: v (rows h*128+2d+1, no norm, NSEQ=512, TRANSPOSED output (b,h,d,m))
// ===========================================================================
#define BM 128
#define BN 128
#define KC 32
#define KCP2 40          // half elements per smem row (80 B)
#define CLD2 136         // epilogue half stride (272 B)
#define PROJ_SMEM (BM * CLD2 * 2)   // 34816 B

template <int MODE>
__global__ __launch_bounds__(256, 2) void proj_fp16(
    const float* __restrict__ A, const float* __restrict__ W0,
    const float* __restrict__ W1)
{
    extern __shared__ char smraw[];
    __half* As = (__half*)smraw;                  // BM x KCP2
    __half* Bs = As + BM * KCP2;                  // BN x KCP2
    constexpr int NSEQ = (MODE == 0) ? NQ : NKV;

    const int m0 = blockIdx.x * BM;
    const int n0 = blockIdx.y * BN;
    const int t = threadIdx.x;
    const int lr = t >> 3;            // 0..31
    const int lc = (t & 7) << 2;      // float4 col 0..28

    const float* wrow[4];
#pragma unroll
    for (int i = 0; i < 4; i++) {
        int j = n0 + lr + i * 32;
        if (MODE == 0) {
            wrow[i] = W0 + (size_t)j * DIM;
        } else {
            int h = j >> 6, d = j & 63;
            int g = h * 128 + 2 * d + (MODE == 2 ? 1 : 0);
            wrow[i] = (g < DIM) ? (W0 + (size_t)g * DIM)
                                : (W1 + (size_t)(g - DIM) * DIM);
        }
    }

    wmma::fragment<wmma::accumulator, 16, 16, 16, float> c[2][4];
#pragma unroll
    for (int i = 0; i < 2; i++)
#pragma unroll
        for (int j = 0; j < 4; j++) wmma::fill_fragment(c[i][j], 0.0f);

    const int warp = t >> 5;
    const int wr = warp & 3;    // 32-row group
    const int wc = warp >> 2;   // 64-col group

    for (int k0 = 0; k0 < DIM; k0 += KC) {
#pragma unroll
        for (int i = 0; i < 4; i++) {
            float4 v = *(const float4*)&A[(size_t)(m0 + lr + i * 32) * DIM + k0 + lc];
            __half* p = &As[(lr + i * 32) * KCP2 + lc];
            p[0] = __float2half_rn(v.x); p[1] = __float2half_rn(v.y);
            p[2] = __float2half_rn(v.z); p[3] = __float2half_rn(v.w);
        }
#pragma unroll
        for (int i = 0; i < 4; i++) {
            float4 v = *(const float4*)&wrow[i][k0 + lc];
            __half* p = &Bs[(lr + i * 32) * KCP2 + lc];
            p[0] = __float2half_rn(v.x); p[1] = __float2half_rn(v.y);
            p[2] = __float2half_rn(v.z); p[3] = __float2half_rn(v.w);
        }
        __syncthreads();
#pragma unroll
        for (int ks = 0; ks < KC; ks += 16) {
            wmma::fragment<wmma::matrix_a, 16, 16, 16, __half, wmma::row_major> a0, a1;
            wmma::load_matrix_sync(a0, &As[(wr * 32) * KCP2 + ks], KCP2);
            wmma::load_matrix_sync(a1, &As[(wr * 32 + 16) * KCP2 + ks], KCP2);
#pragma unroll
            for (int nt = 0; nt < 4; nt++) {
                wmma::fragment<wmma::matrix_b, 16, 16, 16, __half, wmma::col_major> b;
                wmma::load_matrix_sync(b, &Bs[(wc * 64 + nt * 16) * KCP2 + ks], KCP2);
                wmma::mma_sync(c[0][nt], a0, b, c[0][nt]);
                wmma::mma_sync(c[1][nt], a1, b, c[1][nt]);
            }
        }
        __syncthreads();
    }

    // epilogue: convert acc -> half, stage, per-head RMSNorm, write half scratch
    __half* Cs = (__half*)smraw;   // BM x CLD2 halves
#pragma unroll
    for (int i = 0; i < 2; i++)
#pragma unroll
        for (int nt = 0; nt < 4; nt++) {
            wmma::fragment<wmma::accumulator, 16, 16, 16, __half> ch;
#pragma unroll
            for (int e = 0; e < ch.num_elements; e++)
                ch.x[e] = __float2half_rn(c[i][nt].x[e]);
            wmma::store_matrix_sync(&Cs[(wr * 32 + i * 16) * CLD2 + wc * 64 + nt * 16],
                                    ch, CLD2, wmma::mem_row_major);
        }
    __syncthreads();

    __shared__ float sscale[BM * 2];
    {
        int row = t >> 1, g = t & 1;
        float s = 1.0f;
        if (MODE != 2) {
            const __half* cr = &Cs[row * CLD2 + g * 64];
            float ss = 0.0f;
#pragma unroll
            for (int d = 0; d < 64; d++) { float v = __half2float(cr[d]); ss += v * v; }
            s = rsqrtf(ss * (1.0f / 64.0f) + 1e-6f);
            if (MODE == 0) s *= 0.125f;   // fold softmax scale into q
        }
        sscale[row * 2 + g] = s;
    }
    __syncthreads();

#pragma unroll
    for (int it = 0; it < 16; it++) {
        int f = t + it * 256;        // 4096 chunks of 4 halves
        int row = f >> 5;
        int j = (f & 31) << 2;       // half col in tile
        int g = j >> 6;
        int d = j & 63;
        int gi = m0 + row;
        int bb = gi / NSEQ, n = gi % NSEQ;
        int h = (n0 >> 6) + g;
        float sc = sscale[row * 2 + g];
        const __half* cr = &Cs[row * CLD2 + j];
        __half o[4];
#pragma unroll
        for (int u = 0; u < 4; u++)
            o[u] = __float2half_rn(__half2float(cr[u]) * sc);
        if (MODE == 2) {
            // transposed: g_v[((bb*NH + h)*HD + d+u)*NKV + n]
#pragma unroll
            for (int u = 0; u < 4; u++)
                g_v[(((size_t)bb * NH + h) * HD + d + u) * NKV + n] = o[u];
        } else {
            __half* dst = (MODE == 0) ? g_q : g_k;
            *(uint2*)&dst[(((size_t)bb * NH + h) * NSEQ + n) * HD + d] = *(uint2*)o;
        }
    }
}

// ===========================================================================
// FlashAttention-2 style fused attention: register-resident S/P, online
// softmax, raw mma.m16n8k16. Per CTA: 64 queries, 4 warps (16 rows each).
// K tile row-major in smem; V pre-transposed in gmem -> Vt tile [d][kv].
// ===========================================================================
#define ATQ 64
#define KVT 64
#define TLD 72   // smem half stride (144 B): bank index = 4*group + tig, conflict-free

__device__ __forceinline__ void mma16816(float* c, const uint32_t* a,
                                         uint32_t b0, uint32_t b1)
{
    asm volatile(
        "mma.sync.aligned.m16n8k16.row.col.f32.f16.f16.f32 "
        "{%0,%1,%2,%3}, {%4,%5,%6,%7}, {%8,%9}, {%0,%1,%2,%3};"
        : "+f"(c[0]), "+f"(c[1]), "+f"(c[2]), "+f"(c[3])
        : "r"(a[0]), "r"(a[1]), "r"(a[2]), "r"(a[3]), "r"(b0), "r"(b1));
}

__global__ __launch_bounds__(128) void attn_fa(float* __restrict__ out)
{
    __shared__ __half Ks[KVT * TLD];   // [kv][d]
    __shared__ __half Vs[HD * TLD];    // [d][kv]

    const int t = threadIdx.x;
    const int warp = t >> 5, lane = t & 31;
    const int group = lane >> 2, tig = lane & 3;
    const int q0 = blockIdx.x * ATQ;
    const int h = blockIdx.y, b = blockIdx.z;

    const __half* qbase = g_q + (((size_t)b * NH + h) * NQ + q0 + warp * 16) * HD;
    const __half* kbase = g_k + ((size_t)b * NH + h) * NKV * HD;
    const __half* vtbase = g_v + ((size_t)b * NH + h) * HD * NKV;  // [d][m]

    // Q fragments: rows (group, group+8), k-cols 16i + {tig*2, tig*2+8}
    uint32_t qa[4][4];
    {
        const __half* qrA = qbase + group * HD;
        const __half* qrB = qbase + (group + 8) * HD;
#pragma unroll
        for (int i = 0; i < 4; i++) {
            qa[i][0] = *(const uint32_t*)&qrA[i * 16 + tig * 2];
            qa[i][1] = *(const uint32_t*)&qrB[i * 16 + tig * 2];
            qa[i][2] = *(const uint32_t*)&qrA[i * 16 + 8 + tig * 2];
            qa[i][3] = *(const uint32_t*)&qrB[i * 16 + 8 + tig * 2];
        }
    }

    float o[8][4];
#pragma unroll
    for (int j = 0; j < 8; j++)
        o[j][0] = o[j][1] = o[j][2] = o[j][3] = 0.0f;
    float mA = -1e30f, mB = -1e30f, lA = 0.0f, lB = 0.0f;

    for (int kt = 0; kt < 8; kt++) {
        __syncthreads();
        // load K tile (row-major) and Vt tile (already transposed in gmem)
#pragma unroll
        for (int it = 0; it < 4; it++) {
            int f = t + it * 128;
            int r = f >> 3, c8 = (f & 7) * 8;
            *(uint4*)&Ks[r * TLD + c8] = *(const uint4*)&kbase[(kt * 64 + r) * HD + c8];
            *(uint4*)&Vs[r * TLD + c8] = *(const uint4*)&vtbase[(size_t)r * NKV + kt * 64 + c8];
        }
        __syncthreads();

        // S = Q K^T : 8 n8-fragments
        float s[8][4];
#pragma unroll
        for (int j = 0; j < 8; j++) {
            s[j][0] = s[j][1] = s[j][2] = s[j][3] = 0.0f;
            const __half* kr = &Ks[(j * 8 + group) * TLD + tig * 2];
#pragma unroll
            for (int i = 0; i < 4; i++) {
                uint32_t b0 = *(const uint32_t*)&kr[i * 16];
                uint32_t b1 = *(const uint32_t*)&kr[i * 16 + 8];
                mma16816(s[j], qa[i], b0, b1);
            }
        }

        // online softmax (rows rA=group, rB=group+8; quad owns a row)
        float tAm = -1e30f, tBm = -1e30f;
#pragma unroll
        for (int j = 0; j < 8; j++) {
            tAm = fmaxf(tAm, fmaxf(s[j][0], s[j][1]));
            tBm = fmaxf(tBm, fmaxf(s[j][2], s[j][3]));
        }
        tAm = fmaxf(tAm, __shfl_xor_sync(0xffffffffu, tAm, 1));
        tAm = fmaxf(tAm, __shfl_xor_sync(0xffffffffu, tAm, 2));
        tBm = fmaxf(tBm, __shfl_xor_sync(0xffffffffu, tBm, 1));
        tBm = fmaxf(tBm, __shfl_xor_sync(0xffffffffu, tBm, 2));
        float nmA = fmaxf(mA, tAm), nmB = fmaxf(mB, tBm);
        float cA = __expf(mA - nmA), cB = __expf(mB - nmB);
        mA = nmA; mB = nmB;
        lA *= cA; lB *= cB;
#pragma unroll
        for (int j = 0; j < 8; j++) {
            o[j][0] *= cA; o[j][1] *= cA;
            o[j][2] *= cB; o[j][3] *= cB;
        }

        // P = exp(S - m) as half2 fragments (C layout == next A layout)
        uint32_t ph[8][2];
        float sumA = 0.0f, sumB = 0.0f;
#pragma unroll
        for (int j = 0; j < 8; j++) {
            float e0 = __expf(s[j][0] - nmA);
            float e1 = __expf(s[j][1] - nmA);
            float e2 = __expf(s[j][2] - nmB);
            float e3 = __expf(s[j][3] - nmB);
            sumA += e0 + e1; sumB += e2 + e3;
            __half2 p01 = __floats2half2_rn(e0, e1);
            __half2 p23 = __floats2half2_rn(e2, e3);
            ph[j][0] = *(uint32_t*)&p01;
            ph[j][1] = *(uint32_t*)&p23;
        }
        lA += sumA; lB += sumB;

        // O += P V : A k16-frag i2 = S-frags {2*i2, 2*i2+1}
#pragma unroll
        for (int i2 = 0; i2 < 4; i2++) {
            uint32_t pa[4] = { ph[2 * i2][0], ph[2 * i2][1],
                               ph[2 * i2 + 1][0], ph[2 * i2 + 1][1] };
#pragma unroll
            for (int j3 = 0; j3 < 8; j3++) {
                const __half* vr = &Vs[(j3 * 8 + group) * TLD + tig * 2];
                uint32_t b0 = *(const uint32_t*)&vr[i2 * 16];
                uint32_t b1 = *(const uint32_t*)&vr[i2 * 16 + 8];
                mma16816(o[j3], pa, b0, b1);
            }
        }
    }

    // final row sums across quad
    lA += __shfl_xor_sync(0xffffffffu, lA, 1);
    lA += __shfl_xor_sync(0xffffffffu, lA, 2);
    lB += __shfl_xor_sync(0xffffffffu, lB, 1);
    lB += __shfl_xor_sync(0xffffffffu, lB, 2);
    float rA = 1.0f / lA, rB = 1.0f / lB;

    float* obase = out + ((size_t)b * NQ + q0 + warp * 16) * DIM + h * HD;
#pragma unroll
    for (int j3 = 0; j3 < 8; j3++) {
        float2 vA = { o[j3][0] * rA, o[j3][1] * rA };
        float2 vB = { o[j3][2] * rB, o[j3][3] * rB };
        *(float2*)&obase[(size_t)group * DIM + j3 * 8 + tig * 2] = vA;
        *(float2*)&obase[(size_t)(group + 8) * DIM + j3 * 8 + tig * 2] = vB;
    }
}

// ---------------------------------------------------------------------------
extern "C" void kernel_launch(void* const* d_in, const int* in_sizes, int n_in,
                              void* d_out, int out_size)
{
    const float* x  = (const float*)d_in[0];
    const float* cx = (const float*)d_in[1];
    const float* Wq = (const float*)d_in[2];
    const float* Wk = (const float*)d_in[3];
    const float* Wv = (const float*)d_in[4];
    float* out = (float*)d_out;

    cudaFuncSetAttribute((const void*)proj_fp16<0>,
                         cudaFuncAttributeMaxDynamicSharedMemorySize, PROJ_SMEM);
    cudaFuncSetAttribute((const void*)proj_fp16<1>,
                         cudaFuncAttributeMaxDynamicSharedMemorySize, PROJ_SMEM);
    cudaFuncSetAttribute((const void*)proj_fp16<2>,
                         cudaFuncAttributeMaxDynamicSharedMemorySize, PROJ_SMEM);

    // q projection: 8192 rows -> 64 x 16 tiles
    proj_fp16<0><<<dim3(64, 16), 256, PROJ_SMEM>>>(x, Wq, Wq);
    // k / v projections: 1024 rows -> 8 x 16 tiles, interleaved row gather
    proj_fp16<1><<<dim3(8, 16), 256, PROJ_SMEM>>>(cx, Wk, Wv);
    proj_fp16<2><<<dim3(8, 16), 256, PROJ_SMEM>>>(cx, Wk, Wv);
    // fused attention (FA2-style, register-resident S)
    attn_fa<<<dim3(NQ / ATQ, NH, NB), 128>>>(out);
}

// round 6
// speedup vs baseline: 5.1034x; 1.4621x over previous
#include <cuda_runtime.h>
#include <cuda_fp16.h>
#include <cstdint>
#include <mma.h>
using namespace nvcuda;

#define DIM 2048
#define NH 32
#define HD 64
#define NB 2
#define NQ 4096
#define NKV 512

// -------- device scratch (allocation-free rule) --------
__device__ __half h_x [(size_t)NB * NQ  * DIM];   // x  in fp16
__device__ __half h_cx[(size_t)NB * NKV * DIM];   // context in fp16
__device__ __half h_wq[(size_t)DIM * DIM];        // Wq fp16 (row j)
__device__ __half h_wk[(size_t)DIM * DIM];        // gathered: row j=h*64+d <- [Wk;Wv] row h*128+2d
__device__ __half h_wv[(size_t)DIM * DIM];        // gathered: row h*128+2d+1
__device__ __half g_q[(size_t)NB * NH * NQ  * HD]; // (b,h,n,d) rmsnorm(q)*0.125
__device__ __half g_k[(size_t)NB * NH * NKV * HD]; // (b,h,m,d) rmsnorm(k)
__device__ __half g_v[(size_t)NB * NH * HD * NKV]; // (b,h,d,m) v TRANSPOSED

// ===========================================================================
// Conversion prepass
// ===========================================================================
__global__ __launch_bounds__(256) void conv_f2h(const float* __restrict__ src,
                                                __half* __restrict__ dst)
{
    size_t i = ((size_t)blockIdx.x * 256 + threadIdx.x) * 4;
    float4 v = *(const float4*)&src[i];
    __half o[4] = { __float2half_rn(v.x), __float2half_rn(v.y),
                    __float2half_rn(v.z), __float2half_rn(v.w) };
    *(uint2*)&dst[i] = *(uint2*)o;
}

// gathered kv weights: for out row j (h = j>>6, d = j&63): g = h*128 + 2d
// h_wk[j] = [Wk;Wv][g], h_wv[j] = [Wk;Wv][g+1]
__global__ __launch_bounds__(256) void conv_wkv(const float* __restrict__ Wk,
                                                const float* __restrict__ Wv)
{
    int j = blockIdx.y;
    int c = (blockIdx.x * 256 + threadIdx.x) * 4;
    int h = j >> 6, d = j & 63;
    int g = h * 128 + 2 * d;
    const float* srcK = (g < DIM) ? (Wk + (size_t)g * DIM) : (Wv + (size_t)(g - DIM) * DIM);
    const float* srcV = (g + 1 < DIM) ? (Wk + (size_t)(g + 1) * DIM)
                                      : (Wv + (size_t)(g + 1 - DIM) * DIM);
    float4 vk = *(const float4*)&srcK[c];
    float4 vv = *(const float4*)&srcV[c];
    __half ok[4] = { __float2half_rn(vk.x), __float2half_rn(vk.y),
                     __float2half_rn(vk.z), __float2half_rn(vk.w) };
    __half ov[4] = { __float2half_rn(vv.x), __float2half_rn(vv.y),
                     __float2half_rn(vv.z), __float2half_rn(vv.w) };
    *(uint2*)&h_wk[(size_t)j * DIM + c] = *(uint2*)ok;
    *(uint2*)&h_wv[(size_t)j * DIM + c] = *(uint2*)ov;
}

// ===========================================================================
// GEMM (fp16 wmma, cp.async 2-stage pipeline): C[M][2048] = A * B^T
// MODE 0: q (norm*0.125, NSEQ=4096) 1: k (norm) 2: v (no norm, transposed out)
// ===========================================================================
#define BM 128
#define KC 32
#define KCP2 40                       // halves per smem row (80 B)
#define ROWB 80                       // bytes per smem row
#define ABYTES (BM * ROWB)            // 10240
#define STAGE (2 * ABYTES)            // 20480
#define CLD2 136
#define PROJ_SMEM (2 * STAGE)         // 40960 (epilogue 34816 fits under it)
#define NCHUNK (DIM / KC)

#define CP16(d, s) asm volatile("cp.async.cg.shared.global [%0], [%1], 16;" :: "r"(d), "l"(s))
#define CP_COMMIT() asm volatile("cp.async.commit_group;" ::: "memory")
#define CP_WAIT(n)  asm volatile("cp.async.wait_group %0;" :: "n"(n) : "memory")

template <int MODE>
__global__ __launch_bounds__(256, 2) void proj_fp16(
    const __half* __restrict__ A, const __half* __restrict__ Bm)
{
    extern __shared__ char smraw[];
    uint32_t sbase;
    asm("{ .reg .u64 t; cvta.to.shared.u64 t, %1; cvt.u32.u64 %0, t; }"
        : "=r"(sbase) : "l"(smraw));
    constexpr int NSEQ = (MODE == 0) ? NQ : NKV;

    const int m0 = blockIdx.x * BM;
    const int n0 = blockIdx.y * BM;
    const int t = threadIdx.x;
    const int warp = t >> 5;
    const int wr = warp & 3;
    const int wc = warp >> 2;

    wmma::fragment<wmma::accumulator, 16, 16, 16, float> c[2][4];
#pragma unroll
    for (int i = 0; i < 2; i++)
#pragma unroll
        for (int j = 0; j < 4; j++) wmma::fill_fragment(c[i][j], 0.0f);

    // stage issuance: 512 16B-chunks per matrix per stage, 2 per thread each
    const int r0 = t >> 2, c0 = t & 3;          // chunk (row, 16B-slot)
    const int r1 = (t + 256) >> 2, c1 = (t + 256) & 3;
    const __half* arow0 = A + (size_t)(m0 + r0) * DIM + c0 * 8;
    const __half* arow1 = A + (size_t)(m0 + r1) * DIM + c1 * 8;
    const __half* brow0 = Bm + (size_t)(n0 + r0) * DIM + c0 * 8;
    const __half* brow1 = Bm + (size_t)(n0 + r1) * DIM + c1 * 8;
    const uint32_t da0 = sbase + r0 * ROWB + c0 * 16;
    const uint32_t da1 = sbase + r1 * ROWB + c1 * 16;

#define ISSUE(s, k0) do { \
        CP16(da0 + (s) * STAGE, arow0 + (k0)); \
        CP16(da1 + (s) * STAGE, arow1 + (k0)); \
        CP16(da0 + (s) * STAGE + ABYTES, brow0 + (k0)); \
        CP16(da1 + (s) * STAGE + ABYTES, brow1 + (k0)); \
        CP_COMMIT(); \
    } while (0)

    ISSUE(0, 0);

    for (int i = 0; i < NCHUNK; i++) {
        const int p = i & 1;
        if (i + 1 < NCHUNK) { ISSUE(p ^ 1, (i + 1) * KC); CP_WAIT(1); }
        else                { CP_WAIT(0); }
        __syncthreads();

        const __half* As = (const __half*)(smraw + p * STAGE);
        const __half* Bs = (const __half*)(smraw + p * STAGE + ABYTES);
#pragma unroll
        for (int ks = 0; ks < KC; ks += 16) {
            wmma::fragment<wmma::matrix_a, 16, 16, 16, __half, wmma::row_major> a0, a1;
            wmma::load_matrix_sync(a0, &As[(wr * 32) * KCP2 + ks], KCP2);
            wmma::load_matrix_sync(a1, &As[(wr * 32 + 16) * KCP2 + ks], KCP2);
#pragma unroll
            for (int nt = 0; nt < 4; nt++) {
                wmma::fragment<wmma::matrix_b, 16, 16, 16, __half, wmma::col_major> b;
                wmma::load_matrix_sync(b, &Bs[(wc * 64 + nt * 16) * KCP2 + ks], KCP2);
                wmma::mma_sync(c[0][nt], a0, b, c[0][nt]);
                wmma::mma_sync(c[1][nt], a1, b, c[1][nt]);
            }
        }
        __syncthreads();
    }

    // epilogue: stage C as half, per-head RMSNorm, write scratch
    __half* Cs = (__half*)smraw;
#pragma unroll
    for (int i = 0; i < 2; i++)
#pragma unroll
        for (int nt = 0; nt < 4; nt++) {
            wmma::fragment<wmma::accumulator, 16, 16, 16, __half> ch;
#pragma unroll
            for (int e = 0; e < ch.num_elements; e++)
                ch.x[e] = __float2half_rn(c[i][nt].x[e]);
            wmma::store_matrix_sync(&Cs[(wr * 32 + i * 16) * CLD2 + wc * 64 + nt * 16],
                                    ch, CLD2, wmma::mem_row_major);
        }
    __syncthreads();

    __shared__ float sscale[BM * 2];
    {
        int row = t >> 1, g = t & 1;
        float s = 1.0f;
        if (MODE != 2) {
            const __half* cr = &Cs[row * CLD2 + g * 64];
            float ss = 0.0f;
#pragma unroll
            for (int d = 0; d < 64; d++) { float v = __half2float(cr[d]); ss += v * v; }
            s = rsqrtf(ss * (1.0f / 64.0f) + 1e-6f);
            if (MODE == 0) s *= 0.125f;
        }
        sscale[row * 2 + g] = s;
    }
    __syncthreads();

#pragma unroll
    for (int it = 0; it < 16; it++) {
        int f = t + it * 256;
        int row = f >> 5;
        int j = (f & 31) << 2;
        int g = j >> 6;
        int d = j & 63;
        int gi = m0 + row;
        int bb = gi / NSEQ, n = gi % NSEQ;
        int h = (n0 >> 6) + g;
        float sc = sscale[row * 2 + g];
        const __half* cr = &Cs[row * CLD2 + j];
        __half o[4];
#pragma unroll
        for (int u = 0; u < 4; u++)
            o[u] = __float2half_rn(__half2float(cr[u]) * sc);
        if (MODE == 2) {
#pragma unroll
            for (int u = 0; u < 4; u++)
                g_v[(((size_t)bb * NH + h) * HD + d + u) * NKV + n] = o[u];
        } else {
            __half* dst = (MODE == 0) ? g_q : g_k;
            *(uint2*)&dst[(((size_t)bb * NH + h) * NSEQ + n) * HD + d] = *(uint2*)o;
        }
    }
}

// ===========================================================================
// FlashAttention-2 style fused attention (unchanged from R5)
// ===========================================================================
#define ATQ 64
#define KVT 64
#define TLD 72

__device__ __forceinline__ void mma16816(float* c, const uint32_t* a,
                                         uint32_t b0, uint32_t b1)
{
    asm volatile(
        "mma.sync.aligned.m16n8k16.row.col.f32.f16.f16.f32 "
        "{%0,%1,%2,%3}, {%4,%5,%6,%7}, {%8,%9}, {%0,%1,%2,%3};"
        : "+f"(c[0]), "+f"(c[1]), "+f"(c[2]), "+f"(c[3])
        : "r"(a[0]), "r"(a[1]), "r"(a[2]), "r"(a[3]), "r"(b0), "r"(b1));
}

__global__ __launch_bounds__(128) void attn_fa(float* __restrict__ out)
{
    __shared__ __half Ks[KVT * TLD];
    __shared__ __half Vs[HD * TLD];

    const int t = threadIdx.x;
    const int warp = t >> 5, lane = t & 31;
    const int group = lane >> 2, tig = lane & 3;
    const int q0 = blockIdx.x * ATQ;
    const int h = blockIdx.y, b = blockIdx.z;

    const __half* qbase = g_q + (((size_t)b * NH + h) * NQ + q0 + warp * 16) * HD;
    const __half* kbase = g_k + ((size_t)b * NH + h) * NKV * HD;
    const __half* vtbase = g_v + ((size_t)b * NH + h) * HD * NKV;

    uint32_t qa[4][4];
    {
        const __half* qrA = qbase + group * HD;
        const __half* qrB = qbase + (group + 8) * HD;
#pragma unroll
        for (int i = 0; i < 4; i++) {
            qa[i][0] = *(const uint32_t*)&qrA[i * 16 + tig * 2];
            qa[i][1] = *(const uint32_t*)&qrB[i * 16 + tig * 2];
            qa[i][2] = *(const uint32_t*)&qrA[i * 16 + 8 + tig * 2];
            qa[i][3] = *(const uint32_t*)&qrB[i * 16 + 8 + tig * 2];
        }
    }

    float o[8][4];
#pragma unroll
    for (int j = 0; j < 8; j++)
        o[j][0] = o[j][1] = o[j][2] = o[j][3] = 0.0f;
    float mA = -1e30f, mB = -1e30f, lA = 0.0f, lB = 0.0f;

    for (int kt = 0; kt < 8; kt++) {
        __syncthreads();
#pragma unroll
        for (int it = 0; it < 4; it++) {
            int f = t + it * 128;
            int r = f >> 3, c8 = (f & 7) * 8;
            *(uint4*)&Ks[r * TLD + c8] = *(const uint4*)&kbase[(kt * 64 + r) * HD + c8];
            *(uint4*)&Vs[r * TLD + c8] = *(const uint4*)&vtbase[(size_t)r * NKV + kt * 64 + c8];
        }
        __syncthreads();

        float s[8][4];
#pragma unroll
        for (int j = 0; j < 8; j++) {
            s[j][0] = s[j][1] = s[j][2] = s[j][3] = 0.0f;
            const __half* kr = &Ks[(j * 8 + group) * TLD + tig * 2];
#pragma unroll
            for (int i = 0; i < 4; i++) {
                uint32_t b0 = *(const uint32_t*)&kr[i * 16];
                uint32_t b1 = *(const uint32_t*)&kr[i * 16 + 8];
                mma16816(s[j], qa[i], b0, b1);
            }
        }

        float tAm = -1e30f, tBm = -1e30f;
#pragma unroll
        for (int j = 0; j < 8; j++) {
            tAm = fmaxf(tAm, fmaxf(s[j][0], s[j][1]));
            tBm = fmaxf(tBm, fmaxf(s[j][2], s[j][3]));
        }
        tAm = fmaxf(tAm, __shfl_xor_sync(0xffffffffu, tAm, 1));
        tAm = fmaxf(tAm, __shfl_xor_sync(0xffffffffu, tAm, 2));
        tBm = fmaxf(tBm, __shfl_xor_sync(0xffffffffu, tBm, 1));
        tBm = fmaxf(tBm, __shfl_xor_sync(0xffffffffu, tBm, 2));
        float nmA = fmaxf(mA, tAm), nmB = fmaxf(mB, tBm);
        float cA = __expf(mA - nmA), cB = __expf(mB - nmB);
        mA = nmA; mB = nmB;
        lA *= cA; lB *= cB;
#pragma unroll
        for (int j = 0; j < 8; j++) {
            o[j][0] *= cA; o[j][1] *= cA;
            o[j][2] *= cB; o[j][3] *= cB;
        }

        uint32_t ph[8][2];
        float sumA = 0.0f, sumB = 0.0f;
#pragma unroll
        for (int j = 0; j < 8; j++) {
            float e0 = __expf(s[j][0] - nmA);
            float e1 = __expf(s[j][1] - nmA);
            float e2 = __expf(s[j][2] - nmB);
            float e3 = __expf(s[j][3] - nmB);
            sumA += e0 + e1; sumB += e2 + e3;
            __half2 p01 = __floats2half2_rn(e0, e1);
            __half2 p23 = __floats2half2_rn(e2, e3);
            ph[j][0] = *(uint32_t*)&p01;
            ph[j][1] = *(uint32_t*)&p23;
        }
        lA += sumA; lB += sumB;

#pragma unroll
        for (int i2 = 0; i2 < 4; i2++) {
            uint32_t pa[4] = { ph[2 * i2][0], ph[2 * i2][1],
                               ph[2 * i2 + 1][0], ph[2 * i2 + 1][1] };
#pragma unroll
            for (int j3 = 0; j3 < 8; j3++) {
                const __half* vr = &Vs[(j3 * 8 + group) * TLD + tig * 2];
                uint32_t b0 = *(const uint32_t*)&vr[i2 * 16];
                uint32_t b1 = *(const uint32_t*)&vr[i2 * 16 + 8];
                mma16816(o[j3], pa, b0, b1);
            }
        }
    }

    lA += __shfl_xor_sync(0xffffffffu, lA, 1);
    lA += __shfl_xor_sync(0xffffffffu, lA, 2);
    lB += __shfl_xor_sync(0xffffffffu, lB, 1);
    lB += __shfl_xor_sync(0xffffffffu, lB, 2);
    float rA = 1.0f / lA, rB = 1.0f / lB;

    float* obase = out + ((size_t)b * NQ + q0 + warp * 16) * DIM + h * HD;
#pragma unroll
    for (int j3 = 0; j3 < 8; j3++) {
        float2 vA = { o[j3][0] * rA, o[j3][1] * rA };
        float2 vB = { o[j3][2] * rB, o[j3][3] * rB };
        *(float2*)&obase[(size_t)group * DIM + j3 * 8 + tig * 2] = vA;
        *(float2*)&obase[(size_t)(group + 8) * DIM + j3 * 8 + tig * 2] = vB;
    }
}

// ---------------------------------------------------------------------------
extern "C" void kernel_launch(void* const* d_in, const int* in_sizes, int n_in,
                              void* d_out, int out_size)
{
    const float* x  = (const float*)d_in[0];
    const float* cx = (const float*)d_in[1];
    const float* Wq = (const float*)d_in[2];
    const float* Wk = (const float*)d_in[3];
    const float* Wv = (const float*)d_in[4];
    float* out = (float*)d_out;

    __half *dx, *dcx, *dwq;
    cudaGetSymbolAddress((void**)&dx,  h_x);
    cudaGetSymbolAddress((void**)&dcx, h_cx);
    cudaGetSymbolAddress((void**)&dwq, h_wq);

    // fp32 -> fp16 conversion prepass
    conv_f2h<<<(NB * NQ * DIM) / 1024, 256>>>(x, dx);
    conv_f2h<<<(NB * NKV * DIM) / 1024, 256>>>(cx, dcx);
    conv_f2h<<<(DIM * DIM) / 1024, 256>>>(Wq, dwq);
    conv_wkv<<<dim3(2, DIM), 256>>>(Wk, Wv);

    cudaFuncSetAttribute((const void*)proj_fp16<0>,
                         cudaFuncAttributeMaxDynamicSharedMemorySize, PROJ_SMEM);
    cudaFuncSetAttribute((const void*)proj_fp16<1>,
                         cudaFuncAttributeMaxDynamicSharedMemorySize, PROJ_SMEM);
    cudaFuncSetAttribute((const void*)proj_fp16<2>,
                         cudaFuncAttributeMaxDynamicSharedMemorySize, PROJ_SMEM);

    __half *dwk, *dwv;
    cudaGetSymbolAddress((void**)&dwk, h_wk);
    cudaGetSymbolAddress((void**)&dwv, h_wv);

    // projections (cp.async pipelined, fp16 inputs)
    proj_fp16<0><<<dim3(64, 16), 256, PROJ_SMEM>>>(dx, dwq);
    proj_fp16<1><<<dim3(8, 16), 256, PROJ_SMEM>>>(dcx, dwk);
    proj_fp16<2><<<dim3(8, 16), 256, PROJ_SMEM>>>(dcx, dwv);
    // fused attention (FA2-style, register-resident S)
    attn_fa<<<dim3(NQ / ATQ, NH, NB), 128>>>(out);
}